// round 6
// baseline (speedup 1.0000x reference)
#include <cuda_runtime.h>
#include <math.h>

#define BB 64
#define HH 1024
#define BH (BB*HH)                       // 65536

// d_out layout: [c_new (B*H*H)][n_new (B*H)][m_new (B)][h (B*H)]
#define OFF_N  ((size_t)BB*(size_t)HH*(size_t)HH)
#define OFF_M  (OFF_N + (size_t)BH)
#define OFF_H  (OFF_M + (size_t)BB)

// scratch (no allocations allowed -> device globals)
__device__ __align__(16) float g_qk[BH];
__device__ float g_ig[BB];
__device__ float g_fg[BB];
__device__ __align__(16) float g_act[5 * BH];        // 0=query 1=key 2=value 3=out 4=skip

__device__ __forceinline__ unsigned f2tf(float f) {
    unsigned u;
    asm("cvt.rna.tf32.f32 %0, %1;" : "=r"(u) : "f"(f));
    return u;
}
__device__ __forceinline__ float tfbits(float f) { return __uint_as_float(f2tf(f)); }

__device__ __forceinline__ void mma_tf32(float* d, const unsigned* a, const unsigned* b) {
    asm("mma.sync.aligned.m16n8k8.row.col.f32.tf32.tf32.f32 "
        "{%0,%1,%2,%3},{%4,%5,%6,%7},{%8,%9},{%0,%1,%2,%3};"
        : "+f"(d[0]), "+f"(d[1]), "+f"(d[2]), "+f"(d[3])
        : "r"(a[0]), "r"(a[1]), "r"(a[2]), "r"(a[3]), "r"(b[0]), "r"(b[1]));
}

// ---------------------------------------------------------------------------
// Kernel A: conv+silu -> qk ; gate scalars i_g, f_g, m_new
// ---------------------------------------------------------------------------
__global__ void kA(const float* __restrict__ x, const float* __restrict__ m,
                   const float* __restrict__ cw, const float* __restrict__ cb,
                   const float* __restrict__ Wi, const float* __restrict__ bi,
                   const float* __restrict__ Wf, const float* __restrict__ bf,
                   float* __restrict__ m_out)
{
    __shared__ float xs[HH];
    __shared__ float si[8], sf[8];
    int b = blockIdx.x, t = threadIdx.x;

    ((float4*)xs)[t] = ((const float4*)(x + b * HH))[t];
    __syncthreads();

    float c0 = cw[0], c1 = cw[1], c2 = cw[2], c3 = cw[3], cbv = cb[0];
    float pi = 0.f, pf = 0.f;
#pragma unroll
    for (int j = 0; j < 4; j++) {
        int w = t * 4 + j;
        // SAME pad for K=4: pad_lo=1, pad_hi=2 ; correlation (no flip)
        float v = cbv + xs[w] * c1;
        if (w >= 1)      v += xs[w - 1] * c0;
        if (w + 1 < HH)  v += xs[w + 1] * c2;
        if (w + 2 < HH)  v += xs[w + 2] * c3;
        float s = v / (1.f + expf(-v));   // silu
        g_qk[b * HH + w] = s;
        pi += xs[w] * Wi[w];
        pf += xs[w] * Wf[w];
    }
#pragma unroll
    for (int o = 16; o; o >>= 1) {
        pi += __shfl_down_sync(~0u, pi, o);
        pf += __shfl_down_sync(~0u, pf, o);
    }
    if ((t & 31) == 0) { si[t >> 5] = pi; sf[t >> 5] = pf; }
    __syncthreads();
    if (t == 0) {
        float it = bi[0], ft = bf[0];
#pragma unroll
        for (int w = 0; w < 8; w++) { it += si[w]; ft += sf[w]; }
        float mb = m[b];
        float mn = fmaxf(ft + mb, it);
        g_ig[b] = expf(it - mn);
        g_fg[b] = expf(ft + mb - mn);
        m_out[b] = mn;
    }
}

// ---------------------------------------------------------------------------
// Kernel B: 5 GEMMs via tf32 mma.sync, FULL K per block, fused epilogue.
// BM=64 BN=32 BK=32. 128 threads = 4 warps (2x2), warp tile 32x16.
// Register-prefetch pipeline over 32 k-iterations.
// grid: (32, 5) = 160 blocks. Writes bias+activation directly to g_act.
// ---------------------------------------------------------------------------
__global__ void __launch_bounds__(128, 2)
kGEMM(const float* __restrict__ x,
      const float* __restrict__ Wq, const float* __restrict__ Wk,
      const float* __restrict__ Wv, const float* __restrict__ Wo,
      const float* __restrict__ Ws,
      const float* __restrict__ bq, const float* __restrict__ bk,
      const float* __restrict__ bv, const float* __restrict__ bo,
      const float* __restrict__ bs)
{
    const int z = blockIdx.y;
    const float* A = (z == 2 || z == 3) ? x : g_qk;
    const float* W = (z == 0) ? Wq : (z == 1) ? Wk : (z == 2) ? Wv : (z == 3) ? Wo : Ws;
    const float* bias = (z == 0) ? bq : (z == 1) ? bk : (z == 2) ? bv : (z == 3) ? bo : bs;
    const int nt = blockIdx.x * 32;
    const int t = threadIdx.x;
    const int lane = t & 31, warp = t >> 5;
    const int wm = (warp >> 1) * 32;     // warp row base {0,32}
    const int wn = (warp & 1) * 16;      // warp col base {0,16}
    const int gr = lane >> 2, c4 = lane & 3;

    __shared__ float As[64][36];         // [m][k]: frag banks 4*gr+c4 (bijective)
    __shared__ float Bs[32][40];         // [k][n]: frag banks 8*c4+gr (bijective)

    float acc[2][2][4] = {};
    float4 aR[4], bR[2];

    const int arow = t >> 3, akc = (t & 7) * 4;       // A tile coords (i stride 16 rows)
    const int bkr = t >> 3, bnc = (t & 7) * 4;        // B tile coords

    // prologue loads (kt = 0)
#pragma unroll
    for (int i = 0; i < 4; i++)
        aR[i] = *(const float4*)(A + (arow + i * 16) * HH + akc);
#pragma unroll
    for (int i = 0; i < 2; i++)
        bR[i] = *(const float4*)(W + (size_t)(bkr + i * 16) * HH + nt + bnc);

    for (int it = 0; it < 32; it++) {
        // store current tiles to smem (convert to tf32 bits)
#pragma unroll
        for (int i = 0; i < 4; i++) {
            float4 w4 = make_float4(tfbits(aR[i].x), tfbits(aR[i].y),
                                    tfbits(aR[i].z), tfbits(aR[i].w));
            *(float4*)&As[arow + i * 16][akc] = w4;
        }
#pragma unroll
        for (int i = 0; i < 2; i++) {
            float4 w4 = make_float4(tfbits(bR[i].x), tfbits(bR[i].y),
                                    tfbits(bR[i].z), tfbits(bR[i].w));
            *(float4*)&Bs[bkr + i * 16][bnc] = w4;
        }
        __syncthreads();

        // prefetch next k-tile into registers
        if (it + 1 < 32) {
            int kt = (it + 1) * 32;
#pragma unroll
            for (int i = 0; i < 4; i++)
                aR[i] = *(const float4*)(A + (arow + i * 16) * HH + kt + akc);
#pragma unroll
            for (int i = 0; i < 2; i++)
                bR[i] = *(const float4*)(W + (size_t)(kt + bkr + i * 16) * HH + nt + bnc);
        }

        // compute from smem
#pragma unroll
        for (int kk = 0; kk < 32; kk += 8) {
            unsigned a[2][4], bf2[2][2];
#pragma unroll
            for (int mi = 0; mi < 2; mi++) {
                int r0 = wm + mi * 16 + gr;
                a[mi][0] = __float_as_uint(As[r0][kk + c4]);
                a[mi][1] = __float_as_uint(As[r0 + 8][kk + c4]);
                a[mi][2] = __float_as_uint(As[r0][kk + c4 + 4]);
                a[mi][3] = __float_as_uint(As[r0 + 8][kk + c4 + 4]);
            }
#pragma unroll
            for (int ni = 0; ni < 2; ni++) {
                int ncol = wn + ni * 8 + gr;
                bf2[ni][0] = __float_as_uint(Bs[kk + c4][ncol]);
                bf2[ni][1] = __float_as_uint(Bs[kk + c4 + 4][ncol]);
            }
#pragma unroll
            for (int mi = 0; mi < 2; mi++)
#pragma unroll
                for (int ni = 0; ni < 2; ni++)
                    mma_tf32(acc[mi][ni], a[mi], bf2[ni]);
        }
        __syncthreads();
    }

    // fused epilogue: bias + activation -> g_act
    float* G = g_act + (size_t)z * BH;
#pragma unroll
    for (int mi = 0; mi < 2; mi++) {
        int row = wm + mi * 16 + gr;
#pragma unroll
        for (int ni = 0; ni < 2; ni++) {
            int col = nt + wn + ni * 8 + 2 * c4;
            float2 bb = *(const float2*)(bias + col);
            float v0 = acc[mi][ni][0] + bb.x, v1 = acc[mi][ni][1] + bb.y;
            float v2 = acc[mi][ni][2] + bb.x, v3 = acc[mi][ni][3] + bb.y;
            if (z == 1) { v0 *= 0.03125f; v1 *= 0.03125f; v2 *= 0.03125f; v3 *= 0.03125f; }
            if (z == 3) {
                v0 = 1.f / (1.f + expf(-v0)); v1 = 1.f / (1.f + expf(-v1));
                v2 = 1.f / (1.f + expf(-v2)); v3 = 1.f / (1.f + expf(-v3));
            }
            *(float2*)(G + (size_t)row * HH + col) = make_float2(v0, v1);
            *(float2*)(G + (size_t)(row + 8) * HH + col) = make_float2(v2, v3);
        }
    }
}

// ---------------------------------------------------------------------------
// Kernel D: HBM-bound pass. 1 row/warp, all 8 LDG.128 batched up front.
// Preamble computes scaler from k,q,n rows; rb==0 blocks write n_new.
// c_new = f_g*c + (i_g*v_i)*k ; h_i = out_i*(c_new_i.q)*scaler + skip_i.
// grid: (128, 64), block 256
// ---------------------------------------------------------------------------
__global__ void __launch_bounds__(256, 4)
kD(const float* __restrict__ c, const float* __restrict__ n,
   float* __restrict__ out)
{
    __shared__ float ks[HH];
    __shared__ float qs[HH];
    __shared__ float red[16];
    int rb = blockIdx.x, b = blockIdx.y;
    int t = threadIdx.x, lane = t & 31, wid = t >> 5;

    float4 k4 = ((const float4*)(g_act + 1 * BH + b * HH))[t];
    float4 q4 = ((const float4*)(g_act + 0 * BH + b * HH))[t];
    float4 n4 = ((const float4*)(n + b * HH))[t];
    ((float4*)ks)[t] = k4;
    ((float4*)qs)[t] = q4;

    float fg = g_fg[b], ig = g_ig[b];

    if (rb == 0) {   // write n_new for this batch
        float4 nn;
        nn.x = fg * n4.x + ig * k4.x;
        nn.y = fg * n4.y + ig * k4.y;
        nn.z = fg * n4.z + ig * k4.z;
        nn.w = fg * n4.w + ig * k4.w;
        ((float4*)(out + OFF_N + (size_t)b * HH))[t] = nn;
    }

    float pkq = k4.x * q4.x + k4.y * q4.y + k4.z * q4.z + k4.w * q4.w;
    float pnq = n4.x * q4.x + n4.y * q4.y + n4.z * q4.z + n4.w * q4.w;
#pragma unroll
    for (int o = 16; o; o >>= 1) {
        pkq += __shfl_xor_sync(~0u, pkq, o);
        pnq += __shfl_xor_sync(~0u, pnq, o);
    }
    if (lane == 0) { red[wid] = pkq; red[8 + wid] = pnq; }
    __syncthreads();

    float kq = 0.f, nq = 0.f;
#pragma unroll
    for (int w = 0; w < 8; w++) { kq += red[w]; nq += red[8 + w]; }
    float sc = 1.f / fmaxf(fabsf(fg * nq + ig * kq), 1.f);

    const int i = rb * 8 + wid;                       // this warp's row
    const size_t base = ((size_t)b * HH + i) * (size_t)HH;
    const float igv = ig * g_act[2 * BH + b * HH + i];
    float acc = 0.f;

    float4 cv[8];
#pragma unroll
    for (int j = 0; j < 8; j++)
        cv[j] = __ldcs((const float4*)(c + base + j * 128 + lane * 4));
#pragma unroll
    for (int j = 0; j < 8; j++) {
        int k0 = j * 128 + lane * 4;
        float4 kk = *(float4*)(ks + k0);
        float4 qq = *(float4*)(qs + k0);
        float4 r;
        r.x = fg * cv[j].x + igv * kk.x;
        r.y = fg * cv[j].y + igv * kk.y;
        r.z = fg * cv[j].z + igv * kk.z;
        r.w = fg * cv[j].w + igv * kk.w;
        __stcs((float4*)(out + base + k0), r);
        acc += r.x * qq.x + r.y * qq.y + r.z * qq.z + r.w * qq.w;
    }
#pragma unroll
    for (int o = 16; o; o >>= 1) acc += __shfl_xor_sync(~0u, acc, o);
    if (lane == 0) {
        out[OFF_H + (size_t)b * HH + i] =
            g_act[3 * BH + b * HH + i] * (acc * sc) + g_act[4 * BH + b * HH + i];
    }
}

// ---------------------------------------------------------------------------
extern "C" void kernel_launch(void* const* d_in, const int* in_sizes, int n_in,
                              void* d_out, int out_size)
{
    (void)in_sizes; (void)n_in; (void)out_size;
    const float* c      = (const float*)d_in[0];
    const float* n      = (const float*)d_in[1];
    const float* m      = (const float*)d_in[2];
    const float* x      = (const float*)d_in[3];
    const float* Wq     = (const float*)d_in[4];
    const float* bq     = (const float*)d_in[5];
    const float* Wk     = (const float*)d_in[6];
    const float* bk     = (const float*)d_in[7];
    const float* Wv     = (const float*)d_in[8];
    const float* bv     = (const float*)d_in[9];
    const float* conv_w = (const float*)d_in[10];
    const float* conv_b = (const float*)d_in[11];
    const float* Wi     = (const float*)d_in[12];
    const float* bi     = (const float*)d_in[13];
    const float* Wf     = (const float*)d_in[14];
    const float* bf     = (const float*)d_in[15];
    const float* Wo     = (const float*)d_in[16];
    const float* bo     = (const float*)d_in[17];
    const float* Wskip  = (const float*)d_in[18];
    const float* bskip  = (const float*)d_in[19];
    float* out = (float*)d_out;

    kA<<<BB, 256>>>(x, m, conv_w, conv_b, Wi, bi, Wf, bf, out + OFF_M);
    kGEMM<<<dim3(32, 5), 128>>>(x, Wq, Wk, Wv, Wo, Wskip, bq, bk, bv, bo, bskip);
    kD<<<dim3(128, 64), 256>>>(c, n, out);
}